// round 13
// baseline (speedup 1.0000x reference)
#include <cuda_runtime.h>
#include <cuda_bf16.h>
#include <cstdint>
#include <math.h>

#define BB      128
#define DD      (512*512)          // 262144
#define KT      64                 // k elements per stage
#define NTILES  (DD/KT)            // 4096
#define NCTA    148
#define THREADS 512

// ---- scratch (__device__ globals; allocation-free rule) ----
__device__ float g_part[(size_t)NCTA*BB*BB];   // TRANSPOSED partial dots [c][j][i]
__device__ float g_xn2p[NCTA*BB];
__device__ float g_yn2p[NCTA*BB];
__device__ int   g_it1, g_it10, g_tick;

__device__ __forceinline__ uint32_t smem_u32(const void* p) {
    uint32_t a;
    asm("{ .reg .u64 t; cvta.to.shared.u64 t, %1; cvt.u32.u64 %0, t; }" : "=r"(a) : "l"(p));
    return a;
}
#define SW128(o) ((uint32_t)(o) ^ ((((uint32_t)(o)) >> 3) & 0x70))

// fp32 pair -> packed bf16x2 hi + bf16x2 lo (memory order [a,b], a in low half)
__device__ __forceinline__ void cvt_hilo(float a, float b, uint32_t& h, uint32_t& l) {
    asm("cvt.rn.bf16x2.f32 %0, %1, %2;" : "=r"(h) : "f"(b), "f"(a));
    float fa = __uint_as_float(h << 16);
    float fb = __uint_as_float(h & 0xffff0000u);
    float la = a - fa, lb = b - fb;
    asm("cvt.rn.bf16x2.f32 %0, %1, %2;" : "=r"(l) : "f"(lb), "f"(la));
}

#define LDSM4(r, addr)                                                          \
    asm volatile("ldmatrix.sync.aligned.m8n8.x4.shared.b16 {%0,%1,%2,%3}, [%4];"\
        : "=r"((r)[0]), "=r"((r)[1]), "=r"((r)[2]), "=r"((r)[3]) : "r"(addr))

#define MMA16816(d, a0, a1, a2, a3, b0, b1)                                     \
    asm volatile("mma.sync.aligned.m16n8k16.row.col.f32.bf16.bf16.f32 "         \
        "{%0,%1,%2,%3}, {%4,%5,%6,%7}, {%8,%9}, {%0,%1,%2,%3};"                 \
        : "+f"((d)[0]), "+f"((d)[1]), "+f"((d)[2]), "+f"((d)[3])                \
        : "r"(a0), "r"(a1), "r"(a2), "r"(a3), "r"(b0), "r"(b1))

// SMEM: 2 stages x 4 tiles (Xh,Xl,Yh,Yl), each 128 rows x 128B (SW128) = 16KB
#define TILE_OFF(p, w) ((p)*65536 + (w)*16384)
#define SMEM_TOTAL (2*65536)
// epilogue transpose buffer reuses the stage memory: [col][row] fp32, stride 132
#define TSTRIDE 132

__global__ void __launch_bounds__(THREADS, 1)
gemm_tc_kernel(const float* __restrict__ X, const float* __restrict__ Y) {
    extern __shared__ char smem[];
    const uint32_t sbase = smem_u32(smem);
    const int t    = threadIdx.x;
    const int lane = t & 31;
    const int w    = t >> 5;          // warps 0-7: producers; 8-15: consumers
    const int c    = blockIdx.x;

    if (c == 0 && t == 0) { g_it1 = 0; g_it10 = 0; g_tick = 0; }

    const int t0 = (int)(((long long)c       * NTILES) / NCTA);
    const int t1 = (int)(((long long)(c + 1) * NTILES) / NCTA);
    const int NT = t1 - t0;

    if (w >= 8) {
        // ---------------- CONSUMER: 32x64 output tile per warp (champion loop) ----------------
        const int cw = w - 8;
        const int rb = (cw >> 1) * 32;     // row band
        const int cb = (cw & 1) * 64;      // col half

        const int a_row = rb + (lane & 7) + ((lane >> 3) & 1) * 8;
        const int a_kb  = ((lane >> 4) & 1) * 16;
        const int b_row = cb + (lane & 7) + ((lane >> 3) & 1) * 8;
        const int b_kb  = ((lane >> 4) & 1) * 16;

        float acc[16][4];
        #pragma unroll
        for (int j = 0; j < 16; j++)
            #pragma unroll
            for (int q = 0; q < 4; q++) acc[j][q] = 0.0f;

        __syncthreads();   // stage 0 ready

        for (int s = 0; s < NT; s++) {
            const int p = s & 1;
            const uint32_t xh = sbase + TILE_OFF(p, 0);
            const uint32_t xl = sbase + TILE_OFF(p, 1);
            const uint32_t yh = sbase + TILE_OFF(p, 2);
            const uint32_t yl = sbase + TILE_OFF(p, 3);
            #pragma unroll
            for (int kk = 0; kk < 4; kk++) {
                uint32_t ah[8], al[8];
                const uint32_t aoff0 = SW128(a_row * 128 + kk * 32 + a_kb);
                const uint32_t aoff1 = SW128((a_row + 16) * 128 + kk * 32 + a_kb);
                LDSM4(ah + 0, xh + aoff0);
                LDSM4(ah + 4, xh + aoff1);
                LDSM4(al + 0, xl + aoff0);
                LDSM4(al + 4, xl + aoff1);
                #pragma unroll
                for (int nh = 0; nh < 2; nh++) {
                    uint32_t bh[8], bl[8];
                    const uint32_t boff0 = SW128((b_row + nh * 32) * 128 + kk * 32 + b_kb);
                    const uint32_t boff1 = SW128((b_row + nh * 32 + 16) * 128 + kk * 32 + b_kb);
                    LDSM4(bh + 0, yh + boff0);
                    LDSM4(bh + 4, yh + boff1);
                    LDSM4(bl + 0, yl + boff0);
                    LDSM4(bl + 4, yl + boff1);
                    // term order: hh, hl, lh (champion ordering)
                    #pragma unroll
                    for (int m = 0; m < 2; m++) {
                        MMA16816(acc[m*8+nh*4+0], ah[m*4+0],ah[m*4+1],ah[m*4+2],ah[m*4+3], bh[0], bh[2]);
                        MMA16816(acc[m*8+nh*4+1], ah[m*4+0],ah[m*4+1],ah[m*4+2],ah[m*4+3], bh[1], bh[3]);
                        MMA16816(acc[m*8+nh*4+2], ah[m*4+0],ah[m*4+1],ah[m*4+2],ah[m*4+3], bh[4], bh[6]);
                        MMA16816(acc[m*8+nh*4+3], ah[m*4+0],ah[m*4+1],ah[m*4+2],ah[m*4+3], bh[5], bh[7]);
                    }
                    #pragma unroll
                    for (int m = 0; m < 2; m++) {
                        MMA16816(acc[m*8+nh*4+0], ah[m*4+0],ah[m*4+1],ah[m*4+2],ah[m*4+3], bl[0], bl[2]);
                        MMA16816(acc[m*8+nh*4+1], ah[m*4+0],ah[m*4+1],ah[m*4+2],ah[m*4+3], bl[1], bl[3]);
                        MMA16816(acc[m*8+nh*4+2], ah[m*4+0],ah[m*4+1],ah[m*4+2],ah[m*4+3], bl[4], bl[6]);
                        MMA16816(acc[m*8+nh*4+3], ah[m*4+0],ah[m*4+1],ah[m*4+2],ah[m*4+3], bl[5], bl[7]);
                    }
                    #pragma unroll
                    for (int m = 0; m < 2; m++) {
                        MMA16816(acc[m*8+nh*4+0], al[m*4+0],al[m*4+1],al[m*4+2],al[m*4+3], bh[0], bh[2]);
                        MMA16816(acc[m*8+nh*4+1], al[m*4+0],al[m*4+1],al[m*4+2],al[m*4+3], bh[1], bh[3]);
                        MMA16816(acc[m*8+nh*4+2], al[m*4+0],al[m*4+1],al[m*4+2],al[m*4+3], bh[4], bh[6]);
                        MMA16816(acc[m*8+nh*4+3], al[m*4+0],al[m*4+1],al[m*4+2],al[m*4+3], bh[5], bh[7]);
                    }
                }
            }
            __syncthreads();
        }

        // epilogue phase 1: write fragments transposed into smem [col][row]
        {
            float* st = (float*)smem;
            const int r0 = rb + (lane >> 2);
            const int c0 = cb + (lane & 3) * 2;
            #pragma unroll
            for (int m = 0; m < 2; m++)
                #pragma unroll
                for (int nh = 0; nh < 2; nh++)
                    #pragma unroll
                    for (int jj = 0; jj < 4; jj++) {
                        const int j = m * 8 + nh * 4 + jj;
                        const int col = c0 + nh * 32 + jj * 8;
                        const int row = r0 + m * 16;
                        st[col * TSTRIDE + row]           = acc[j][0];
                        st[(col + 1) * TSTRIDE + row]     = acc[j][1];
                        st[col * TSTRIDE + row + 8]       = acc[j][2];
                        st[(col + 1) * TSTRIDE + row + 8] = acc[j][3];
                    }
        }
    } else {
        // ---------------- PRODUCER: LDG two stages ahead, store one ahead ----------------
        const int tp   = w * 32 + lane;         // 0..255
        const int prow = tp >> 4;               // rows prow + 16*i, i<8
        const int pf4  = tp & 15;

        float snx[8], sny[8];
        #pragma unroll
        for (int i = 0; i < 8; i++) { snx[i] = 0.f; sny[i] = 0.f; }

        float4 vx[2][4], vy[2][4];

        auto load_half = [&](int kt, int h) {
            const long long kb = (long long)kt * KT + pf4 * 4;
            #pragma unroll
            for (int i = 0; i < 4; i++) {
                const int row = prow + 16 * (4 * h + i);
                vx[h][i] = __ldg((const float4*)(X + (long long)row * DD + kb));
                vy[h][i] = __ldg((const float4*)(Y + (long long)row * DD + kb));
            }
        };
        auto store_half = [&](int p, int h) {
            char* xh = smem + TILE_OFF(p, 0);
            char* xl = smem + TILE_OFF(p, 1);
            char* yh = smem + TILE_OFF(p, 2);
            char* yl = smem + TILE_OFF(p, 3);
            #pragma unroll
            for (int i = 0; i < 4; i++) {
                const int ii = 4 * h + i;
                const int row = prow + 16 * ii;
                const uint32_t off = SW128(row * 128 + pf4 * 8);
                const float4 v = vx[h][i];
                snx[ii] += v.x*v.x + v.y*v.y + v.z*v.z + v.w*v.w;
                uint32_t h0, l0, h1, l1;
                cvt_hilo(v.x, v.y, h0, l0);
                cvt_hilo(v.z, v.w, h1, l1);
                *(uint2*)(xh + off) = make_uint2(h0, h1);
                *(uint2*)(xl + off) = make_uint2(l0, l1);
                const float4 u = vy[h][i];
                sny[ii] += u.x*u.x + u.y*u.y + u.z*u.z + u.w*u.w;
                cvt_hilo(u.x, u.y, h0, l0);
                cvt_hilo(u.z, u.w, h1, l1);
                *(uint2*)(yh + off) = make_uint2(h0, h1);
                *(uint2*)(yl + off) = make_uint2(l0, l1);
            }
        };

        load_half(t0, 0); load_half(t0, 1);
        store_half(0, 0); store_half(0, 1);
        if (NT > 1) { load_half(t0 + 1, 0); load_half(t0 + 1, 1); }
        __syncthreads();   // stage 0 ready

        for (int s = 0; s < NT; s++) {
            if (s + 1 < NT) {
                const int p = (s + 1) & 1;
                store_half(p, 0);
                if (s + 2 < NT) load_half(t0 + s + 2, 0);
                store_half(p, 1);
                if (s + 2 < NT) load_half(t0 + s + 2, 1);
            }
            __syncthreads();
        }

        // norm partials: 16 consecutive lanes share each row set
        #pragma unroll
        for (int i = 0; i < 8; i++) {
            float a = snx[i], b = sny[i];
            #pragma unroll
            for (int o = 8; o >= 1; o >>= 1) {
                a += __shfl_xor_sync(0xffffffffu, a, o);
                b += __shfl_xor_sync(0xffffffffu, b, o);
            }
            if (pf4 == 0) {
                const int row = prow + 16 * i;
                g_xn2p[c * BB + row] = a;
                g_yn2p[c * BB + row] = b;
            }
        }
    }

    // epilogue phase 2 (all warps): coalesced store of transposed tile [c][col][row]
    __syncthreads();
    {
        const float* st = (const float*)smem;
        float* base = &g_part[(size_t)c * (BB * BB)];
        const int col = t >> 2;            // 0..127
        const int rb4 = (t & 3) * 32;      // row block
        #pragma unroll
        for (int rr = 0; rr < 32; rr += 4) {
            const float4 v = *(const float4*)&st[col * TSTRIDE + rb4 + rr];
            *(float4*)&base[col * BB + rb4 + rr] = v;
        }
    }
}

// finalize (no separate reduce): CTA j handles sim column j.
// dots[i][j] = sum_c g_part[c][j][i]  (coalesced: consecutive i).
// v_i = dots / max(xn_i * yn_j, eps). JAX ties: lower index wins. Deterministic.
__global__ void finalize_kernel(float* __restrict__ out) {
    __shared__ float s_yn[BB];
    __shared__ float s_vd;
    __shared__ int s_gt, s_eqb;
    const int j = blockIdx.x;
    const int i = threadIdx.x;

    // dots: 148 coalesced loads
    float d = 0.f;
    {
        const float* p = &g_part[(size_t)j * BB + i];
        #pragma unroll 4
        for (int c = 0; c < NCTA; c++) d += p[(size_t)c * (BB * BB)];
    }
    // x norm for row i: coalesced
    float x2 = 0.f;
    #pragma unroll 4
    for (int c = 0; c < NCTA; c++) x2 += g_xn2p[c * BB + i];
    // y norm for column j: cooperative deterministic tree
    float yp = 0.f;
    for (int c = i; c < NCTA; c += BB) yp += g_yn2p[c * BB + j];
    s_yn[i] = yp;
    if (i == 0) { s_gt = 0; s_eqb = 0; }
    __syncthreads();
    #pragma unroll
    for (int off = 64; off >= 1; off >>= 1) {
        if (i < off) s_yn[i] += s_yn[i + off];
        __syncthreads();
    }
    const float ynj = sqrtf(s_yn[0]);
    const float xni = sqrtf(x2);
    const float v = d / fmaxf(xni * ynj, 1e-8f);

    if (i == j) s_vd = v;
    __syncthreads();
    const float vd = s_vd;

    const bool gt  = (i != j) && (v > vd);
    const bool eqb = (i != j) && (v == vd) && (i < j);
    const unsigned mgt  = __ballot_sync(0xffffffffu, gt);
    const unsigned meqb = __ballot_sync(0xffffffffu, eqb);
    if ((i & 31) == 0) {
        if (mgt)  atomicAdd(&s_gt,  __popc(mgt));
        if (meqb) atomicAdd(&s_eqb, __popc(meqb));
    }
    __syncthreads();

    if (i == 0) {
        const int rank = s_gt + s_eqb;
        atomicAdd(&g_it1,  (rank == 0) ? 1 : 0);
        atomicAdd(&g_it10, (rank < 10) ? 1 : 0);
        __threadfence();
        const int tick = atomicAdd(&g_tick, 1);
        if (tick == BB - 1) {
            __threadfence();
            out[0] = (float)g_it1  / (float)BB;
            out[1] = (float)g_it10 / (float)BB;
        }
    }
}

extern "C" void kernel_launch(void* const* d_in, const int* in_sizes, int n_in,
                              void* d_out, int out_size) {
    const float* Z = (const float*)d_in[0];
    const float* Y = (const float*)d_in[1];
    float* out = (float*)d_out;

    cudaFuncSetAttribute(gemm_tc_kernel, cudaFuncAttributeMaxDynamicSharedMemorySize, SMEM_TOTAL);
    gemm_tc_kernel<<<NCTA, THREADS, SMEM_TOTAL>>>(Z, Y);
    finalize_kernel<<<BB, BB>>>(out);
}

// round 14
// speedup vs baseline: 1.2076x; 1.2076x over previous
#include <cuda_runtime.h>
#include <cuda_bf16.h>
#include <cstdint>
#include <math.h>

#define BB      128
#define DD      (512*512)          // 262144
#define KT      64                 // k elements per stage
#define NTILES  (DD/KT)            // 4096
#define NCTA    148
#define THREADS 512
#define CPC     37                 // 148 = 4*37

// ---- scratch (__device__ globals; allocation-free rule) ----
__device__ float g_part[(size_t)NCTA*BB*BB];   // TRANSPOSED partial dots [c][j][i]
__device__ float g_xn2p[NCTA*BB];
__device__ float g_yn2p[NCTA*BB];
__device__ int   g_it1, g_it10, g_tick;

__device__ __forceinline__ uint32_t smem_u32(const void* p) {
    uint32_t a;
    asm("{ .reg .u64 t; cvta.to.shared.u64 t, %1; cvt.u32.u64 %0, t; }" : "=r"(a) : "l"(p));
    return a;
}
#define SW128(o) ((uint32_t)(o) ^ ((((uint32_t)(o)) >> 3) & 0x70))

// fp32 pair -> packed bf16x2 hi + bf16x2 lo (memory order [a,b], a in low half)
__device__ __forceinline__ void cvt_hilo(float a, float b, uint32_t& h, uint32_t& l) {
    asm("cvt.rn.bf16x2.f32 %0, %1, %2;" : "=r"(h) : "f"(b), "f"(a));
    float fa = __uint_as_float(h << 16);
    float fb = __uint_as_float(h & 0xffff0000u);
    float la = a - fa, lb = b - fb;
    asm("cvt.rn.bf16x2.f32 %0, %1, %2;" : "=r"(l) : "f"(lb), "f"(la));
}

#define LDSM4(r, addr)                                                          \
    asm volatile("ldmatrix.sync.aligned.m8n8.x4.shared.b16 {%0,%1,%2,%3}, [%4];"\
        : "=r"((r)[0]), "=r"((r)[1]), "=r"((r)[2]), "=r"((r)[3]) : "r"(addr))

#define MMA16816(d, a0, a1, a2, a3, b0, b1)                                     \
    asm volatile("mma.sync.aligned.m16n8k16.row.col.f32.bf16.bf16.f32 "         \
        "{%0,%1,%2,%3}, {%4,%5,%6,%7}, {%8,%9}, {%0,%1,%2,%3};"                 \
        : "+f"((d)[0]), "+f"((d)[1]), "+f"((d)[2]), "+f"((d)[3])                \
        : "r"(a0), "r"(a1), "r"(a2), "r"(a3), "r"(b0), "r"(b1))

// SMEM: 2 stages x 4 tiles (Xh,Xl,Yh,Yl), each 128 rows x 128B (SW128) = 16KB
#define TILE_OFF(p, w) ((p)*65536 + (w)*16384)
#define SMEM_TOTAL (2*65536)
// epilogue transpose buffer reuses the stage memory: [col][row] fp32, stride 132
#define TSTRIDE 132

__global__ void __launch_bounds__(THREADS, 1)
gemm_tc_kernel(const float* __restrict__ X, const float* __restrict__ Y) {
    extern __shared__ char smem[];
    const uint32_t sbase = smem_u32(smem);
    const int t    = threadIdx.x;
    const int lane = t & 31;
    const int w    = t >> 5;          // warps 0-7: producers; 8-15: consumers
    const int c    = blockIdx.x;

    if (c == 0 && t == 0) { g_it1 = 0; g_it10 = 0; g_tick = 0; }

    const int t0 = (int)(((long long)c       * NTILES) / NCTA);
    const int t1 = (int)(((long long)(c + 1) * NTILES) / NCTA);
    const int NT = t1 - t0;

    if (w >= 8) {
        // ---------------- CONSUMER: 32x64 output tile per warp (champion loop) ----------------
        const int cw = w - 8;
        const int rb = (cw >> 1) * 32;     // row band
        const int cb = (cw & 1) * 64;      // col half

        const int a_row = rb + (lane & 7) + ((lane >> 3) & 1) * 8;
        const int a_kb  = ((lane >> 4) & 1) * 16;
        const int b_row = cb + (lane & 7) + ((lane >> 3) & 1) * 8;
        const int b_kb  = ((lane >> 4) & 1) * 16;

        float acc[16][4];
        #pragma unroll
        for (int j = 0; j < 16; j++)
            #pragma unroll
            for (int q = 0; q < 4; q++) acc[j][q] = 0.0f;

        __syncthreads();   // stage 0 ready

        for (int s = 0; s < NT; s++) {
            const int p = s & 1;
            const uint32_t xh = sbase + TILE_OFF(p, 0);
            const uint32_t xl = sbase + TILE_OFF(p, 1);
            const uint32_t yh = sbase + TILE_OFF(p, 2);
            const uint32_t yl = sbase + TILE_OFF(p, 3);
            #pragma unroll
            for (int kk = 0; kk < 4; kk++) {
                uint32_t ah[8], al[8];
                const uint32_t aoff0 = SW128(a_row * 128 + kk * 32 + a_kb);
                const uint32_t aoff1 = SW128((a_row + 16) * 128 + kk * 32 + a_kb);
                LDSM4(ah + 0, xh + aoff0);
                LDSM4(ah + 4, xh + aoff1);
                LDSM4(al + 0, xl + aoff0);
                LDSM4(al + 4, xl + aoff1);
                #pragma unroll
                for (int nh = 0; nh < 2; nh++) {
                    uint32_t bh[8], bl[8];
                    const uint32_t boff0 = SW128((b_row + nh * 32) * 128 + kk * 32 + b_kb);
                    const uint32_t boff1 = SW128((b_row + nh * 32 + 16) * 128 + kk * 32 + b_kb);
                    LDSM4(bh + 0, yh + boff0);
                    LDSM4(bh + 4, yh + boff1);
                    LDSM4(bl + 0, yl + boff0);
                    LDSM4(bl + 4, yl + boff1);
                    // term order: hh, hl, lh (champion ordering)
                    #pragma unroll
                    for (int m = 0; m < 2; m++) {
                        MMA16816(acc[m*8+nh*4+0], ah[m*4+0],ah[m*4+1],ah[m*4+2],ah[m*4+3], bh[0], bh[2]);
                        MMA16816(acc[m*8+nh*4+1], ah[m*4+0],ah[m*4+1],ah[m*4+2],ah[m*4+3], bh[1], bh[3]);
                        MMA16816(acc[m*8+nh*4+2], ah[m*4+0],ah[m*4+1],ah[m*4+2],ah[m*4+3], bh[4], bh[6]);
                        MMA16816(acc[m*8+nh*4+3], ah[m*4+0],ah[m*4+1],ah[m*4+2],ah[m*4+3], bh[5], bh[7]);
                    }
                    #pragma unroll
                    for (int m = 0; m < 2; m++) {
                        MMA16816(acc[m*8+nh*4+0], ah[m*4+0],ah[m*4+1],ah[m*4+2],ah[m*4+3], bl[0], bl[2]);
                        MMA16816(acc[m*8+nh*4+1], ah[m*4+0],ah[m*4+1],ah[m*4+2],ah[m*4+3], bl[1], bl[3]);
                        MMA16816(acc[m*8+nh*4+2], ah[m*4+0],ah[m*4+1],ah[m*4+2],ah[m*4+3], bl[4], bl[6]);
                        MMA16816(acc[m*8+nh*4+3], ah[m*4+0],ah[m*4+1],ah[m*4+2],ah[m*4+3], bl[5], bl[7]);
                    }
                    #pragma unroll
                    for (int m = 0; m < 2; m++) {
                        MMA16816(acc[m*8+nh*4+0], al[m*4+0],al[m*4+1],al[m*4+2],al[m*4+3], bh[0], bh[2]);
                        MMA16816(acc[m*8+nh*4+1], al[m*4+0],al[m*4+1],al[m*4+2],al[m*4+3], bh[1], bh[3]);
                        MMA16816(acc[m*8+nh*4+2], al[m*4+0],al[m*4+1],al[m*4+2],al[m*4+3], bh[4], bh[6]);
                        MMA16816(acc[m*8+nh*4+3], al[m*4+0],al[m*4+1],al[m*4+2],al[m*4+3], bh[5], bh[7]);
                    }
                }
            }
            __syncthreads();
        }

        // epilogue phase 1: write fragments transposed into smem [col][row]
        {
            float* st = (float*)smem;
            const int r0 = rb + (lane >> 2);
            const int c0 = cb + (lane & 3) * 2;
            #pragma unroll
            for (int m = 0; m < 2; m++)
                #pragma unroll
                for (int nh = 0; nh < 2; nh++)
                    #pragma unroll
                    for (int jj = 0; jj < 4; jj++) {
                        const int j = m * 8 + nh * 4 + jj;
                        const int col = c0 + nh * 32 + jj * 8;
                        const int row = r0 + m * 16;
                        st[col * TSTRIDE + row]           = acc[j][0];
                        st[(col + 1) * TSTRIDE + row]     = acc[j][1];
                        st[col * TSTRIDE + row + 8]       = acc[j][2];
                        st[(col + 1) * TSTRIDE + row + 8] = acc[j][3];
                    }
        }
    } else {
        // ---------------- PRODUCER: LDG two stages ahead, store one ahead ----------------
        const int tp   = w * 32 + lane;         // 0..255
        const int prow = tp >> 4;               // rows prow + 16*i, i<8
        const int pf4  = tp & 15;

        float snx[8], sny[8];
        #pragma unroll
        for (int i = 0; i < 8; i++) { snx[i] = 0.f; sny[i] = 0.f; }

        float4 vx[2][4], vy[2][4];

        auto load_half = [&](int kt, int h) {
            const long long kb = (long long)kt * KT + pf4 * 4;
            #pragma unroll
            for (int i = 0; i < 4; i++) {
                const int row = prow + 16 * (4 * h + i);
                vx[h][i] = __ldg((const float4*)(X + (long long)row * DD + kb));
                vy[h][i] = __ldg((const float4*)(Y + (long long)row * DD + kb));
            }
        };
        auto store_half = [&](int p, int h) {
            char* xh = smem + TILE_OFF(p, 0);
            char* xl = smem + TILE_OFF(p, 1);
            char* yh = smem + TILE_OFF(p, 2);
            char* yl = smem + TILE_OFF(p, 3);
            #pragma unroll
            for (int i = 0; i < 4; i++) {
                const int ii = 4 * h + i;
                const int row = prow + 16 * ii;
                const uint32_t off = SW128(row * 128 + pf4 * 8);
                const float4 v = vx[h][i];
                snx[ii] += v.x*v.x + v.y*v.y + v.z*v.z + v.w*v.w;
                uint32_t h0, l0, h1, l1;
                cvt_hilo(v.x, v.y, h0, l0);
                cvt_hilo(v.z, v.w, h1, l1);
                *(uint2*)(xh + off) = make_uint2(h0, h1);
                *(uint2*)(xl + off) = make_uint2(l0, l1);
                const float4 u = vy[h][i];
                sny[ii] += u.x*u.x + u.y*u.y + u.z*u.z + u.w*u.w;
                cvt_hilo(u.x, u.y, h0, l0);
                cvt_hilo(u.z, u.w, h1, l1);
                *(uint2*)(yh + off) = make_uint2(h0, h1);
                *(uint2*)(yl + off) = make_uint2(l0, l1);
            }
        };

        load_half(t0, 0); load_half(t0, 1);
        store_half(0, 0); store_half(0, 1);
        if (NT > 1) { load_half(t0 + 1, 0); load_half(t0 + 1, 1); }
        __syncthreads();   // stage 0 ready

        for (int s = 0; s < NT; s++) {
            if (s + 1 < NT) {
                const int p = (s + 1) & 1;
                store_half(p, 0);
                if (s + 2 < NT) load_half(t0 + s + 2, 0);
                store_half(p, 1);
                if (s + 2 < NT) load_half(t0 + s + 2, 1);
            }
            __syncthreads();
        }

        // norm partials: 16 consecutive lanes share each row set
        #pragma unroll
        for (int i = 0; i < 8; i++) {
            float a = snx[i], b = sny[i];
            #pragma unroll
            for (int o = 8; o >= 1; o >>= 1) {
                a += __shfl_xor_sync(0xffffffffu, a, o);
                b += __shfl_xor_sync(0xffffffffu, b, o);
            }
            if (pf4 == 0) {
                const int row = prow + 16 * i;
                g_xn2p[c * BB + row] = a;
                g_yn2p[c * BB + row] = b;
            }
        }
    }

    // epilogue phase 2 (all warps): coalesced store of transposed tile [c][col][row]
    __syncthreads();
    {
        const float* st = (const float*)smem;
        float* base = &g_part[(size_t)c * (BB * BB)];
        const int col = t >> 2;            // 0..127
        const int rb4 = (t & 3) * 32;      // row block
        #pragma unroll
        for (int rr = 0; rr < 32; rr += 4) {
            const float4 v = *(const float4*)&st[col * TSTRIDE + rb4 + rr];
            *(float4*)&base[col * BB + rb4 + rr] = v;
        }
    }
}

// fused finalize: CTA j handles sim column j; 512 threads = 4 reduction chunks.
// dots[i][j] = sum_c g_part[c][j][i] (coalesced over i).
// v_i = dots / max(xn_i * yn_j, eps). JAX ties: lower index wins. Deterministic.
__global__ void __launch_bounds__(512, 1) finalize_kernel(float* __restrict__ out) {
    __shared__ float s_d[4][BB];
    __shared__ float s_x[4][BB];
    __shared__ float s_y[512];
    __shared__ float s_vd;
    __shared__ int s_gt, s_eqb;
    const int j = blockIdx.x;
    const int t = threadIdx.x;
    const int i = t & 127;
    const int h = t >> 7;              // chunk 0..3

    // dots partial: 37 coalesced loads, unroll 8
    {
        const float* p = &g_part[(size_t)(h * CPC) * (BB * BB) + (size_t)j * BB + i];
        float d = 0.f;
        #pragma unroll 8
        for (int k = 0; k < CPC; k++) d += p[(size_t)k * (BB * BB)];
        s_d[h][i] = d;
    }
    // x-norm partial
    {
        const float* p = &g_xn2p[(h * CPC) * BB + i];
        float x2 = 0.f;
        #pragma unroll 8
        for (int k = 0; k < CPC; k++) x2 += p[k * BB];
        s_x[h][i] = x2;
    }
    // y-norm: one slice per thread, 512-thread tree
    s_y[t] = (t < NCTA) ? g_yn2p[t * BB + j] : 0.f;
    if (t == 0) { s_gt = 0; s_eqb = 0; }
    __syncthreads();
    #pragma unroll
    for (int off = 256; off >= 1; off >>= 1) {
        if (t < off) s_y[t] += s_y[t + off];
        __syncthreads();
    }

    if (h == 0) {
        const float d   = (s_d[0][i] + s_d[1][i]) + (s_d[2][i] + s_d[3][i]);
        const float xni = sqrtf((s_x[0][i] + s_x[1][i]) + (s_x[2][i] + s_x[3][i]));
        const float ynj = sqrtf(s_y[0]);
        const float v = d / fmaxf(xni * ynj, 1e-8f);
        if (i == j) s_vd = v;
        __syncwarp();
        // need vd visible across warps 0-3
        __threadfence_block();
        asm volatile("bar.sync 1, 128;" ::: "memory");
        const float vd = s_vd;

        const bool gt  = (i != j) && (v > vd);
        const bool eqb = (i != j) && (v == vd) && (i < j);
        const unsigned mgt  = __ballot_sync(0xffffffffu, gt);
        const unsigned meqb = __ballot_sync(0xffffffffu, eqb);
        if ((i & 31) == 0) {
            if (mgt)  atomicAdd(&s_gt,  __popc(mgt));
            if (meqb) atomicAdd(&s_eqb, __popc(meqb));
        }
        asm volatile("bar.sync 1, 128;" ::: "memory");

        if (i == 0) {
            const int rank = s_gt + s_eqb;
            atomicAdd(&g_it1,  (rank == 0) ? 1 : 0);
            atomicAdd(&g_it10, (rank < 10) ? 1 : 0);
            __threadfence();
            const int tick = atomicAdd(&g_tick, 1);
            if (tick == BB - 1) {
                __threadfence();
                out[0] = (float)g_it1  / (float)BB;
                out[1] = (float)g_it10 / (float)BB;
            }
        }
    }
}

extern "C" void kernel_launch(void* const* d_in, const int* in_sizes, int n_in,
                              void* d_out, int out_size) {
    const float* Z = (const float*)d_in[0];
    const float* Y = (const float*)d_in[1];
    float* out = (float*)d_out;

    cudaFuncSetAttribute(gemm_tc_kernel, cudaFuncAttributeMaxDynamicSharedMemorySize, SMEM_TOTAL);
    gemm_tc_kernel<<<NCTA, THREADS, SMEM_TOTAL>>>(Z, Y);
    finalize_kernel<<<BB, 512>>>(out);
}

// round 15
// speedup vs baseline: 1.2411x; 1.0278x over previous
#include <cuda_runtime.h>
#include <cuda_bf16.h>
#include <cstdint>
#include <math.h>

#define BB      128
#define DD      (512*512)          // 262144
#define KT      64                 // k elements per stage
#define NTILES  (DD/KT)            // 4096
#define NCTA    148
#define THREADS 512
#define CPC     37                 // 148 = 4*37

// ---- scratch (__device__ globals; zero-initialized at module load) ----
__device__ float g_dots[BB*BB];        // accumulated via REDG; re-zeroed by finalize
__device__ float g_xn2p[NCTA*BB];      // per-slice norm partials (plain stores)
__device__ float g_yn2p[NCTA*BB];
__device__ int   g_it1, g_it10, g_tick;  // re-zeroed by finalize

__device__ __forceinline__ uint32_t smem_u32(const void* p) {
    uint32_t a;
    asm("{ .reg .u64 t; cvta.to.shared.u64 t, %1; cvt.u32.u64 %0, t; }" : "=r"(a) : "l"(p));
    return a;
}
#define SW128(o) ((uint32_t)(o) ^ ((((uint32_t)(o)) >> 3) & 0x70))

// fp32 pair -> packed bf16x2 hi + bf16x2 lo (memory order [a,b], a in low half)
__device__ __forceinline__ void cvt_hilo(float a, float b, uint32_t& h, uint32_t& l) {
    asm("cvt.rn.bf16x2.f32 %0, %1, %2;" : "=r"(h) : "f"(b), "f"(a));
    float fa = __uint_as_float(h << 16);
    float fb = __uint_as_float(h & 0xffff0000u);
    float la = a - fa, lb = b - fb;
    asm("cvt.rn.bf16x2.f32 %0, %1, %2;" : "=r"(l) : "f"(lb), "f"(la));
}

#define LDSM4(r, addr)                                                          \
    asm volatile("ldmatrix.sync.aligned.m8n8.x4.shared.b16 {%0,%1,%2,%3}, [%4];"\
        : "=r"((r)[0]), "=r"((r)[1]), "=r"((r)[2]), "=r"((r)[3]) : "r"(addr))

#define MMA16816(d, a0, a1, a2, a3, b0, b1)                                     \
    asm volatile("mma.sync.aligned.m16n8k16.row.col.f32.bf16.bf16.f32 "         \
        "{%0,%1,%2,%3}, {%4,%5,%6,%7}, {%8,%9}, {%0,%1,%2,%3};"                 \
        : "+f"((d)[0]), "+f"((d)[1]), "+f"((d)[2]), "+f"((d)[3])                \
        : "r"(a0), "r"(a1), "r"(a2), "r"(a3), "r"(b0), "r"(b1))

// SMEM: 2 stages x 4 tiles (Xh,Xl,Yh,Yl), each 128 rows x 128B (SW128) = 16KB
#define TILE_OFF(p, w) ((p)*65536 + (w)*16384)
#define SMEM_TOTAL (2*65536)

__global__ void __launch_bounds__(THREADS, 1)
gemm_tc_kernel(const float* __restrict__ X, const float* __restrict__ Y) {
    extern __shared__ char smem[];
    const uint32_t sbase = smem_u32(smem);
    const int t    = threadIdx.x;
    const int lane = t & 31;
    const int w    = t >> 5;          // warps 0-7: producers; 8-15: consumers
    const int c    = blockIdx.x;

    const int t0 = (int)(((long long)c       * NTILES) / NCTA);
    const int t1 = (int)(((long long)(c + 1) * NTILES) / NCTA);
    const int NT = t1 - t0;

    if (w >= 8) {
        // ---------------- CONSUMER: 32x64 output tile per warp (champion loop) ----------------
        const int cw = w - 8;
        const int rb = (cw >> 1) * 32;     // row band
        const int cb = (cw & 1) * 64;      // col half

        const int a_row = rb + (lane & 7) + ((lane >> 3) & 1) * 8;
        const int a_kb  = ((lane >> 4) & 1) * 16;
        const int b_row = cb + (lane & 7) + ((lane >> 3) & 1) * 8;
        const int b_kb  = ((lane >> 4) & 1) * 16;

        float acc[16][4];
        #pragma unroll
        for (int j = 0; j < 16; j++)
            #pragma unroll
            for (int q = 0; q < 4; q++) acc[j][q] = 0.0f;

        __syncthreads();   // stage 0 ready

        for (int s = 0; s < NT; s++) {
            const int p = s & 1;
            const uint32_t xh = sbase + TILE_OFF(p, 0);
            const uint32_t xl = sbase + TILE_OFF(p, 1);
            const uint32_t yh = sbase + TILE_OFF(p, 2);
            const uint32_t yl = sbase + TILE_OFF(p, 3);
            #pragma unroll
            for (int kk = 0; kk < 4; kk++) {
                uint32_t ah[8], al[8];
                const uint32_t aoff0 = SW128(a_row * 128 + kk * 32 + a_kb);
                const uint32_t aoff1 = SW128((a_row + 16) * 128 + kk * 32 + a_kb);
                LDSM4(ah + 0, xh + aoff0);
                LDSM4(ah + 4, xh + aoff1);
                LDSM4(al + 0, xl + aoff0);
                LDSM4(al + 4, xl + aoff1);
                #pragma unroll
                for (int nh = 0; nh < 2; nh++) {
                    uint32_t bh[8], bl[8];
                    const uint32_t boff0 = SW128((b_row + nh * 32) * 128 + kk * 32 + b_kb);
                    const uint32_t boff1 = SW128((b_row + nh * 32 + 16) * 128 + kk * 32 + b_kb);
                    LDSM4(bh + 0, yh + boff0);
                    LDSM4(bh + 4, yh + boff1);
                    LDSM4(bl + 0, yl + boff0);
                    LDSM4(bl + 4, yl + boff1);
                    // term order: hh, hl, lh (champion ordering)
                    #pragma unroll
                    for (int m = 0; m < 2; m++) {
                        MMA16816(acc[m*8+nh*4+0], ah[m*4+0],ah[m*4+1],ah[m*4+2],ah[m*4+3], bh[0], bh[2]);
                        MMA16816(acc[m*8+nh*4+1], ah[m*4+0],ah[m*4+1],ah[m*4+2],ah[m*4+3], bh[1], bh[3]);
                        MMA16816(acc[m*8+nh*4+2], ah[m*4+0],ah[m*4+1],ah[m*4+2],ah[m*4+3], bh[4], bh[6]);
                        MMA16816(acc[m*8+nh*4+3], ah[m*4+0],ah[m*4+1],ah[m*4+2],ah[m*4+3], bh[5], bh[7]);
                    }
                    #pragma unroll
                    for (int m = 0; m < 2; m++) {
                        MMA16816(acc[m*8+nh*4+0], ah[m*4+0],ah[m*4+1],ah[m*4+2],ah[m*4+3], bl[0], bl[2]);
                        MMA16816(acc[m*8+nh*4+1], ah[m*4+0],ah[m*4+1],ah[m*4+2],ah[m*4+3], bl[1], bl[3]);
                        MMA16816(acc[m*8+nh*4+2], ah[m*4+0],ah[m*4+1],ah[m*4+2],ah[m*4+3], bl[4], bl[6]);
                        MMA16816(acc[m*8+nh*4+3], ah[m*4+0],ah[m*4+1],ah[m*4+2],ah[m*4+3], bl[5], bl[7]);
                    }
                    #pragma unroll
                    for (int m = 0; m < 2; m++) {
                        MMA16816(acc[m*8+nh*4+0], al[m*4+0],al[m*4+1],al[m*4+2],al[m*4+3], bh[0], bh[2]);
                        MMA16816(acc[m*8+nh*4+1], al[m*4+0],al[m*4+1],al[m*4+2],al[m*4+3], bh[1], bh[3]);
                        MMA16816(acc[m*8+nh*4+2], al[m*4+0],al[m*4+1],al[m*4+2],al[m*4+3], bh[4], bh[6]);
                        MMA16816(acc[m*8+nh*4+3], al[m*4+0],al[m*4+1],al[m*4+2],al[m*4+3], bh[5], bh[7]);
                    }
                }
            }
            __syncthreads();
        }

        // epilogue: REDG-accumulate partial dots into g_dots (zeroed by prior finalize)
        {
            const int r0 = rb + (lane >> 2);
            const int c0 = cb + (lane & 3) * 2;
            #pragma unroll
            for (int m = 0; m < 2; m++)
                #pragma unroll
                for (int nh = 0; nh < 2; nh++)
                    #pragma unroll
                    for (int jj = 0; jj < 4; jj++) {
                        const int j = m * 8 + nh * 4 + jj;
                        const int col = c0 + nh * 32 + jj * 8;
                        atomicAdd(&g_dots[(r0 + m*16) * BB + col],     acc[j][0]);
                        atomicAdd(&g_dots[(r0 + m*16) * BB + col + 1], acc[j][1]);
                        atomicAdd(&g_dots[(r0 + m*16 + 8) * BB + col],     acc[j][2]);
                        atomicAdd(&g_dots[(r0 + m*16 + 8) * BB + col + 1], acc[j][3]);
                    }
        }
    } else {
        // ---------------- PRODUCER: LDG two stages ahead, store one ahead ----------------
        const int tp   = w * 32 + lane;         // 0..255
        const int prow = tp >> 4;               // rows prow + 16*i, i<8
        const int pf4  = tp & 15;

        float snx[8], sny[8];
        #pragma unroll
        for (int i = 0; i < 8; i++) { snx[i] = 0.f; sny[i] = 0.f; }

        float4 vx[2][4], vy[2][4];

        auto load_half = [&](int kt, int h) {
            const long long kb = (long long)kt * KT + pf4 * 4;
            #pragma unroll
            for (int i = 0; i < 4; i++) {
                const int row = prow + 16 * (4 * h + i);
                vx[h][i] = __ldg((const float4*)(X + (long long)row * DD + kb));
                vy[h][i] = __ldg((const float4*)(Y + (long long)row * DD + kb));
            }
        };
        auto store_half = [&](int p, int h) {
            char* xh = smem + TILE_OFF(p, 0);
            char* xl = smem + TILE_OFF(p, 1);
            char* yh = smem + TILE_OFF(p, 2);
            char* yl = smem + TILE_OFF(p, 3);
            #pragma unroll
            for (int i = 0; i < 4; i++) {
                const int ii = 4 * h + i;
                const int row = prow + 16 * ii;
                const uint32_t off = SW128(row * 128 + pf4 * 8);
                const float4 v = vx[h][i];
                snx[ii] += v.x*v.x + v.y*v.y + v.z*v.z + v.w*v.w;
                uint32_t h0, l0, h1, l1;
                cvt_hilo(v.x, v.y, h0, l0);
                cvt_hilo(v.z, v.w, h1, l1);
                *(uint2*)(xh + off) = make_uint2(h0, h1);
                *(uint2*)(xl + off) = make_uint2(l0, l1);
                const float4 u = vy[h][i];
                sny[ii] += u.x*u.x + u.y*u.y + u.z*u.z + u.w*u.w;
                cvt_hilo(u.x, u.y, h0, l0);
                cvt_hilo(u.z, u.w, h1, l1);
                *(uint2*)(yh + off) = make_uint2(h0, h1);
                *(uint2*)(yl + off) = make_uint2(l0, l1);
            }
        };

        load_half(t0, 0); load_half(t0, 1);
        store_half(0, 0); store_half(0, 1);
        if (NT > 1) { load_half(t0 + 1, 0); load_half(t0 + 1, 1); }
        __syncthreads();   // stage 0 ready

        for (int s = 0; s < NT; s++) {
            if (s + 1 < NT) {
                const int p = (s + 1) & 1;
                store_half(p, 0);
                if (s + 2 < NT) load_half(t0 + s + 2, 0);
                store_half(p, 1);
                if (s + 2 < NT) load_half(t0 + s + 2, 1);
            }
            __syncthreads();
        }

        // norm partials: 16 consecutive lanes share each row set
        #pragma unroll
        for (int i = 0; i < 8; i++) {
            float a = snx[i], b = sny[i];
            #pragma unroll
            for (int o = 8; o >= 1; o >>= 1) {
                a += __shfl_xor_sync(0xffffffffu, a, o);
                b += __shfl_xor_sync(0xffffffffu, b, o);
            }
            if (pf4 == 0) {
                const int row = prow + 16 * i;
                g_xn2p[c * BB + row] = a;
                g_yn2p[c * BB + row] = b;
            }
        }
    }
}

// finalize: CTA j handles sim column j. dots[i][j] is a single L2 load.
// v_i = dots / max(xn_i * yn_j, eps). JAX ties: lower index wins.
// Last CTA (ticket) writes output and restores zero-state for the next replay.
__global__ void __launch_bounds__(512, 1) finalize_kernel(float* __restrict__ out) {
    __shared__ float s_x[4][BB];
    __shared__ float s_y[512];
    __shared__ float s_vd;
    __shared__ int s_gt, s_eqb, s_last;
    const int j = blockIdx.x;
    const int t = threadIdx.x;
    const int i = t & 127;
    const int h = t >> 7;              // chunk 0..3

    // x-norm partial: 37 coalesced L2 loads per chunk
    {
        const float* p = &g_xn2p[(h * CPC) * BB + i];
        float x2 = 0.f;
        #pragma unroll 8
        for (int k = 0; k < CPC; k++) x2 += p[k * BB];
        s_x[h][i] = x2;
    }
    // y-norm: one slice per thread, 512-thread tree
    s_y[t] = (t < NCTA) ? g_yn2p[t * BB + j] : 0.f;
    if (t == 0) { s_gt = 0; s_eqb = 0; s_last = 0; }
    __syncthreads();
    #pragma unroll
    for (int off = 256; off >= 1; off >>= 1) {
        if (t < off) s_y[t] += s_y[t + off];
        __syncthreads();
    }

    float v = 0.f;
    if (h == 0) {
        const float d   = g_dots[i * BB + j];
        const float xni = sqrtf((s_x[0][i] + s_x[1][i]) + (s_x[2][i] + s_x[3][i]));
        const float ynj = sqrtf(s_y[0]);
        v = d / fmaxf(xni * ynj, 1e-8f);
        if (i == j) s_vd = v;
    }
    __syncthreads();
    if (h == 0) {
        const float vd = s_vd;
        const bool gt  = (i != j) && (v > vd);
        const bool eqb = (i != j) && (v == vd) && (i < j);
        const unsigned mgt  = __ballot_sync(0xffffffffu, gt);
        const unsigned meqb = __ballot_sync(0xffffffffu, eqb);
        if ((i & 31) == 0) {
            if (mgt)  atomicAdd(&s_gt,  __popc(mgt));
            if (meqb) atomicAdd(&s_eqb, __popc(meqb));
        }
    }
    __syncthreads();

    if (t == 0) {
        const int rank = s_gt + s_eqb;
        atomicAdd(&g_it1,  (rank == 0) ? 1 : 0);
        atomicAdd(&g_it10, (rank < 10) ? 1 : 0);
        __threadfence();
        const int tick = atomicAdd(&g_tick, 1);
        if (tick == BB - 1) {
            __threadfence();
            out[0] = (float)g_it1  / (float)BB;
            out[1] = (float)g_it10 / (float)BB;
            g_it1 = 0; g_it10 = 0; g_tick = 0;
            s_last = 1;
        }
    }
    __syncthreads();
    if (s_last) {  // last CTA restores g_dots zero-state (all CTAs have ticked -> all reads done)
        for (int q = t; q < BB * BB; q += 512) g_dots[q] = 0.f;
    }
}

extern "C" void kernel_launch(void* const* d_in, const int* in_sizes, int n_in,
                              void* d_out, int out_size) {
    const float* Z = (const float*)d_in[0];
    const float* Y = (const float*)d_in[1];
    float* out = (float*)d_out;

    cudaFuncSetAttribute(gemm_tc_kernel, cudaFuncAttributeMaxDynamicSharedMemorySize, SMEM_TOTAL);
    gemm_tc_kernel<<<NCTA, THREADS, SMEM_TOTAL>>>(Z, Y);
    finalize_kernel<<<BB, 512>>>(out);
}